// round 5
// baseline (speedup 1.0000x reference)
#include <cuda_runtime.h>
#include <cstddef>

#define TT 9
#define SS 9
#define FF 512
#define H1 32
#define H2 64
#define XROW 1032          // floats per s-pair row (2*FF + 8 pad)
#define BASE7 7.0f

// ---------------- device scratch ----------------
__device__ float g_W1b [TT * 16 * 8 * 32 * 4];   // blocked rotated W1: [t][fb4*j4][m8][lane32]f4
__device__ float g_W2r [TT * H1];
__device__ float g_mW1b[4 * 8 * 8 * 32 * 4];     // blocked rotated mW1: [fb4*j8][m8][lane32]f4
__device__ float g_mW2r[H2];
__device__ float g_team[4096 * TT * FF];
__device__ float g_tq  [4096 * TT];
__device__ float g_sink;

// ---------------- profiling-alignment dummy (ncu -s 5 lands on k1) ----------------
__global__ void kalign() {
    // deterministic no-op with a dead guarded store so it can't be elided
    if (threadIdx.x == 0xFFFFFFFFu) g_sink = 0.0f;
}

// ---------------- f32x2 helpers ----------------
__device__ __forceinline__ unsigned long long ffma2(unsigned long long a,
                                                    unsigned long long b,
                                                    unsigned long long c) {
    unsigned long long d;
    asm("fma.rn.f32x2 %0, %1, %2, %3;" : "=l"(d) : "l"(a), "l"(b), "l"(c));
    return d;
}
__device__ __forceinline__ unsigned long long fadd2(unsigned long long a,
                                                    unsigned long long b) {
    unsigned long long d;
    asm("add.rn.f32x2 %0, %1, %2;" : "=l"(d) : "l"(a), "l"(b));
    return d;
}
__device__ __forceinline__ unsigned long long dup2(float x) {
    unsigned long long r;
    asm("mov.b64 %0, {%1, %1};" : "=l"(r) : "f"(x));
    return r;
}
__device__ __forceinline__ float2 unpk2(unsigned long long r) {
    float2 v;
    asm("mov.b64 {%0, %1}, %2;" : "=f"(v.x), "=f"(v.y) : "l"(r));
    return v;
}

__device__ __forceinline__ float pnorm1(float h, float g, float b) {
    float m = h - BASE7 * floorf(h * (1.0f / BASE7));
    return g * ((m - 3.5f) * (1.0f / 3.5f)) + b;
}

// rotate-absorb: coeff of x_f in dot(rot(x), Wrow)
__device__ __forceinline__ float rotv(const float* __restrict__ Wrow,
                                      const float* __restrict__ ang,
                                      int f, int nplanes) {
    if (f >= 2 * nplanes) return Wrow[f];
    int p = f >> 1; float a = ang[p];
    float c = cosf(a), s = sinf(a);
    float w0 = Wrow[2 * p], w1 = Wrow[2 * p + 1];
    return (f & 1) ? (c * w1 - s * w0) : (c * w0 + s * w1);
}

// ---------------- prep: rotate + re-tile weights ----------------
__global__ void kprep(const float* __restrict__ W1, const float* __restrict__ ang1,
                      const float* __restrict__ W2, const float* __restrict__ ang2,
                      const float* __restrict__ mW1, const float* __restrict__ mang1,
                      const float* __restrict__ mW2, const float* __restrict__ mang2)
{
    int idx = blockIdx.x * 256 + threadIdx.x;
    const int N1 = TT * 16384;
    const int N2 = TT * H1;
    const int N3 = 32768;
    const int N4 = H2;
    if (idx < N1) {
        int c    =  idx        & 3;
        int lane = (idx >> 2)  & 31;
        int m    = (idx >> 7)  & 7;
        int j    = (idx >> 10) & 3;
        int fb   = (idx >> 12) & 3;
        int t    =  idx >> 14;
        int o = 8 * j + (m & 1) * 4 + c;
        int f = fb * 128 + 4 * lane + (m >> 1);
        g_W1b[idx] = rotv(W1 + ((size_t)t * H1 + o) * FF, ang1 + 2 * t, f, 2);
    } else if (idx < N1 + N2) {
        int jj = idx - N1; int t = jj / H1, o = jj - t * H1;
        g_W2r[jj] = rotv(W2 + t * H1, ang2 + 2 * t, o, 2);
    } else if (idx < N1 + N2 + N3) {
        int jj = idx - N1 - N2;
        int c    =  jj        & 3;
        int lane = (jj >> 2)  & 31;
        int m    = (jj >> 7)  & 7;
        int j    = (jj >> 10) & 7;
        int fb   = (jj >> 13) & 3;
        int o = 8 * j + (m & 1) * 4 + c;
        int f = fb * 128 + 4 * lane + (m >> 1);
        g_mW1b[jj] = rotv(mW1 + (size_t)o * FF, mang1, f, 4);
    } else if (idx < N1 + N2 + N3 + N4) {
        int o = idx - N1 - N2 - N3;
        g_mW2r[o] = rotv(mW2, mang2, o, 2);
    }
}

#define PROC1(wc, oo) { \
    unsigned long long wd = dup2(wc); \
    acc[oo][0] = ffma2(xd0, wd, acc[oo][0]); \
    acc[oo][1] = ffma2(xd1, wd, acc[oo][1]); \
    acc[oo][2] = ffma2(xd2, wd, acc[oo][2]); \
    acc[oo][3] = ffma2(xd3, wd, acc[oo][3]); \
    acc8[oo] = fmaf(wc, x8s, acc8[oo]); }
#define PROC4(wv, ohbase) \
    PROC1((wv).x, (ohbase) + 0) PROC1((wv).y, (ohbase) + 1) \
    PROC1((wv).z, (ohbase) + 2) PROC1((wv).w, (ohbase) + 3)

// ---------------- kernel 1: per (b,t) ----------------
__global__ __launch_bounds__(256) void k1(const float* __restrict__ path,
                                          const float* __restrict__ b1,
                                          const float* __restrict__ gamma1,
                                          const float* __restrict__ beta1)
{
    __shared__ float xsp[4 * XROW];          // s-pair rows: (x[2sp][f], x[2sp+1][f])
    __shared__ float xs8[FF + 8];            // s=8 row
    __shared__ float red[2 * 9 * 32 * 5];    // [h][s][o][lane4 pad5]
    __shared__ float scp[SS * 33];
    __shared__ float qsm[16];

    const int t = blockIdx.x, b = blockIdx.y;
    const int tid = threadIdx.x, lane = tid & 31, w = tid >> 5;
    const int j = w & 3, h = w >> 2;

    // stage x: pair layout
    const float* xb = path + (size_t)b * (FF * TT * SS) + t * SS;
    #pragma unroll 2
    for (int i = tid; i < SS * FF; i += 256) {
        int f = i / 9, s = i - f * 9;
        float v = xb[(size_t)f * (TT * SS) + s];
        if (s == 8) xs8[f] = v;
        else xsp[(s >> 1) * XROW + 2 * f + (s & 1)] = v;
    }
    __syncthreads();

    // GEMM1: warp = (o-octet j, f-half h)
    unsigned long long acc[8][4];
    float acc8[8];
    #pragma unroll
    for (int o8 = 0; o8 < 8; ++o8) {
        acc8[o8] = 0.f;
        #pragma unroll
        for (int sp = 0; sp < 4; ++sp) acc[o8][sp] = 0ull;
    }

    const float4* wbT = reinterpret_cast<const float4*>(g_W1b) + (size_t)t * 4096;
    #pragma unroll
    for (int s2 = 0; s2 < 2; ++s2) {
        int fb = 2 * h + s2;
        const float4* wb = wbT + (fb * 4 + j) * 256 + lane;
        int f0 = fb * 128 + 4 * lane;
        #pragma unroll
        for (int fp = 0; fp < 2; ++fp) {
            float4 w0 = wb[(4 * fp + 0) * 32];
            float4 w1 = wb[(4 * fp + 1) * 32];
            float4 w2 = wb[(4 * fp + 2) * 32];
            float4 w3 = wb[(4 * fp + 3) * 32];
            ulonglong2 a0 = *reinterpret_cast<const ulonglong2*>(&xsp[0 * XROW + 2 * f0 + 4 * fp]);
            ulonglong2 a1 = *reinterpret_cast<const ulonglong2*>(&xsp[1 * XROW + 2 * f0 + 4 * fp]);
            ulonglong2 a2 = *reinterpret_cast<const ulonglong2*>(&xsp[2 * XROW + 2 * f0 + 4 * fp]);
            ulonglong2 a3 = *reinterpret_cast<const ulonglong2*>(&xsp[3 * XROW + 2 * f0 + 4 * fp]);
            float2 x8v = *reinterpret_cast<const float2*>(&xs8[f0 + 2 * fp]);
            {
                unsigned long long xd0 = a0.x, xd1 = a1.x, xd2 = a2.x, xd3 = a3.x;
                float x8s = x8v.x;
                PROC4(w0, 0) PROC4(w1, 4)
            }
            {
                unsigned long long xd0 = a0.y, xd1 = a1.y, xd2 = a2.y, xd3 = a3.y;
                float x8s = x8v.y;
                PROC4(w2, 0) PROC4(w3, 4)
            }
        }
    }

    // 3-round butterfly (32 -> 4 partials)
    #pragma unroll
    for (int r = 16; r >= 4; r >>= 1) {
        #pragma unroll
        for (int o8 = 0; o8 < 8; ++o8) {
            #pragma unroll
            for (int sp = 0; sp < 4; ++sp)
                acc[o8][sp] = fadd2(acc[o8][sp],
                                    __shfl_xor_sync(0xffffffffu, acc[o8][sp], r));
            acc8[o8] += __shfl_xor_sync(0xffffffffu, acc8[o8], r);
        }
    }
    if (lane < 4) {
        #pragma unroll
        for (int o8 = 0; o8 < 8; ++o8) {
            int o = 8 * j + o8;
            #pragma unroll
            for (int sp = 0; sp < 4; ++sp) {
                float2 v = unpk2(acc[o8][sp]);
                red[((h * 9 + 2 * sp + 0) * 32 + o) * 5 + lane] = v.x;
                red[((h * 9 + 2 * sp + 1) * 32 + o) * 5 + lane] = v.y;
            }
            red[((h * 9 + 8) * 32 + o) * 5 + lane] = acc8[o8];
        }
    }
    __syncthreads();

    // finalize h -> pnorm -> score partials
    for (int v = tid; v < SS * H1; v += 256) {
        int s = v >> 5, o = v & 31;
        float hh = 0.f;
        #pragma unroll
        for (int hl = 0; hl < 2; ++hl)
            #pragma unroll
            for (int l = 0; l < 4; ++l)
                hh += red[((hl * 9 + s) * 32 + o) * 5 + l];
        hh += b1[t * H1 + o];
        float pn = pnorm1(hh, gamma1[t * H1 + o], beta1[t * H1 + o]);
        scp[s * 33 + o] = pn * g_W2r[t * H1 + o];
    }
    __syncthreads();

    // softmax over s (warp 0)
    if (tid < 32) {
        float sc = -3.0e38f;
        if (lane < SS) {
            float s0 = 0.f;
            #pragma unroll
            for (int o = 0; o < H1; ++o) s0 += scp[lane * 33 + o];
            sc = s0;
        }
        float mx = sc;
        #pragma unroll
        for (int d = 16; d; d >>= 1) mx = fmaxf(mx, __shfl_xor_sync(0xffffffffu, mx, d));
        float e = (lane < SS) ? expf(sc - mx) : 0.f;
        float se = e;
        #pragma unroll
        for (int d = 16; d; d >>= 1) se += __shfl_xor_sync(0xffffffffu, se, d);
        float q = e / se;
        float qt = q;
        #pragma unroll
        for (int d = 16; d; d >>= 1) qt += __shfl_xor_sync(0xffffffffu, qt, d);
        if (lane < SS) qsm[lane] = q;
        if (lane == 0) g_tq[b * TT + t] = qt * (1.0f / SS);
    }
    __syncthreads();

    // team_out
    float* tout = g_team + ((size_t)b * TT + t) * FF;
    float q0 = qsm[0], q1 = qsm[1], q2 = qsm[2], q3 = qsm[3], q4 = qsm[4],
          q5 = qsm[5], q6 = qsm[6], q7 = qsm[7], q8 = qsm[8];
    for (int f = tid; f < FF; f += 256) {
        float2 v0 = *reinterpret_cast<const float2*>(&xsp[0 * XROW + 2 * f]);
        float2 v1 = *reinterpret_cast<const float2*>(&xsp[1 * XROW + 2 * f]);
        float2 v2 = *reinterpret_cast<const float2*>(&xsp[2 * XROW + 2 * f]);
        float2 v3 = *reinterpret_cast<const float2*>(&xsp[3 * XROW + 2 * f]);
        float o = q8 * xs8[f];
        o = fmaf(q0, v0.x, o); o = fmaf(q1, v0.y, o);
        o = fmaf(q2, v1.x, o); o = fmaf(q3, v1.y, o);
        o = fmaf(q4, v2.x, o); o = fmaf(q5, v2.y, o);
        o = fmaf(q6, v3.x, o); o = fmaf(q7, v3.y, o);
        tout[f] = o;
    }
}

// ---------------- kernel 2: per b ----------------
__global__ __launch_bounds__(256) void k2(const float* __restrict__ mb1,
                                          const float* __restrict__ mgamma,
                                          const float* __restrict__ mbeta,
                                          const float* __restrict__ cc,
                                          const float* __restrict__ rc,
                                          const float* __restrict__ ic,
                                          float* __restrict__ out)
{
    __shared__ float tsp[4 * XROW];
    __shared__ float ts8[FF + 8];
    __shared__ float red[9 * 64 * 5];
    __shared__ float msp[9 * 65];
    __shared__ float mwm[16];

    const int b = blockIdx.x;
    const int tid = threadIdx.x, lane = tid & 31, w = tid >> 5;
    const int j = w;

    // stage team_out (coalesced read, pair-layout write)
    const float4* tin4 = reinterpret_cast<const float4*>(g_team + (size_t)b * TT * FF);
    #pragma unroll 2
    for (int i = tid; i < TT * FF / 4; i += 256) {
        int tt = i >> 7, fq = i & 127, f = 4 * fq;
        float4 v = tin4[i];
        if (tt == 8) {
            *reinterpret_cast<float4*>(&ts8[f]) = v;
        } else {
            int sp = tt >> 1, hf = tt & 1;
            tsp[sp * XROW + 2 * (f + 0) + hf] = v.x;
            tsp[sp * XROW + 2 * (f + 1) + hf] = v.y;
            tsp[sp * XROW + 2 * (f + 2) + hf] = v.z;
            tsp[sp * XROW + 2 * (f + 3) + hf] = v.w;
        }
    }
    __syncthreads();

    unsigned long long acc[8][4];
    float acc8[8];
    #pragma unroll
    for (int o8 = 0; o8 < 8; ++o8) {
        acc8[o8] = 0.f;
        #pragma unroll
        for (int sp = 0; sp < 4; ++sp) acc[o8][sp] = 0ull;
    }

    const float4* wbT = reinterpret_cast<const float4*>(g_mW1b);
    #pragma unroll
    for (int fb = 0; fb < 4; ++fb) {
        const float4* wb = wbT + (fb * 8 + j) * 256 + lane;
        int f0 = fb * 128 + 4 * lane;
        #pragma unroll
        for (int fp = 0; fp < 2; ++fp) {
            float4 w0 = wb[(4 * fp + 0) * 32];
            float4 w1 = wb[(4 * fp + 1) * 32];
            float4 w2 = wb[(4 * fp + 2) * 32];
            float4 w3 = wb[(4 * fp + 3) * 32];
            ulonglong2 a0 = *reinterpret_cast<const ulonglong2*>(&tsp[0 * XROW + 2 * f0 + 4 * fp]);
            ulonglong2 a1 = *reinterpret_cast<const ulonglong2*>(&tsp[1 * XROW + 2 * f0 + 4 * fp]);
            ulonglong2 a2 = *reinterpret_cast<const ulonglong2*>(&tsp[2 * XROW + 2 * f0 + 4 * fp]);
            ulonglong2 a3 = *reinterpret_cast<const ulonglong2*>(&tsp[3 * XROW + 2 * f0 + 4 * fp]);
            float2 x8v = *reinterpret_cast<const float2*>(&ts8[f0 + 2 * fp]);
            {
                unsigned long long xd0 = a0.x, xd1 = a1.x, xd2 = a2.x, xd3 = a3.x;
                float x8s = x8v.x;
                PROC4(w0, 0) PROC4(w1, 4)
            }
            {
                unsigned long long xd0 = a0.y, xd1 = a1.y, xd2 = a2.y, xd3 = a3.y;
                float x8s = x8v.y;
                PROC4(w2, 0) PROC4(w3, 4)
            }
        }
    }

    #pragma unroll
    for (int r = 16; r >= 4; r >>= 1) {
        #pragma unroll
        for (int o8 = 0; o8 < 8; ++o8) {
            #pragma unroll
            for (int sp = 0; sp < 4; ++sp)
                acc[o8][sp] = fadd2(acc[o8][sp],
                                    __shfl_xor_sync(0xffffffffu, acc[o8][sp], r));
            acc8[o8] += __shfl_xor_sync(0xffffffffu, acc8[o8], r);
        }
    }
    if (lane < 4) {
        #pragma unroll
        for (int o8 = 0; o8 < 8; ++o8) {
            int o = 8 * j + o8;
            #pragma unroll
            for (int sp = 0; sp < 4; ++sp) {
                float2 v = unpk2(acc[o8][sp]);
                red[((2 * sp + 0) * 64 + o) * 5 + lane] = v.x;
                red[((2 * sp + 1) * 64 + o) * 5 + lane] = v.y;
            }
            red[(8 * 64 + o) * 5 + lane] = acc8[o8];
        }
    }
    __syncthreads();

    for (int v = tid; v < TT * H2; v += 256) {
        int tt = v >> 6, o = v & 63;
        float hh = 0.f;
        #pragma unroll
        for (int l = 0; l < 4; ++l) hh += red[(tt * 64 + o) * 5 + l];
        hh += mb1[o];
        float pn = pnorm1(hh, mgamma[o], mbeta[o]);
        msp[tt * 65 + o] = pn * g_mW2r[o];
    }
    __syncthreads();

    if (tid < 32) {
        float sc = -3.0e38f;
        if (lane < TT) {
            float s0 = 0.f;
            #pragma unroll
            for (int o = 0; o < H2; ++o) s0 += msp[lane * 65 + o];
            sc = s0;
        }
        float mx = sc;
        #pragma unroll
        for (int d = 16; d; d >>= 1) mx = fmaxf(mx, __shfl_xor_sync(0xffffffffu, mx, d));
        float e = (lane < TT) ? expf(sc - mx) : 0.f;
        float se = e;
        #pragma unroll
        for (int d = 16; d; d >>= 1) se += __shfl_xor_sync(0xffffffffu, se, d);
        float mwq = e / se;

        float tq = (lane < TT) ? g_tq[b * TT + lane] : 0.f;
        float ts = tq;
        #pragma unroll
        for (int d = 16; d; d >>= 1) ts += __shfl_xor_sync(0xffffffffu, ts, d);
        float mean = ts * (1.0f / TT);
        float dv = (lane < TT) ? (tq - mean) * (tq - mean) : 0.f;
        float vs = dv;
        #pragma unroll
        for (int d = 16; d; d >>= 1) vs += __shfl_xor_sync(0xffffffffu, vs, d);
        float var = vs * (1.0f / (TT - 1));
        float nv = var / (mean * mean + 1e-8f);
        float total = cc[0] * (float)(TT * (TT - 1) / 2) + rc[0] * (float)TT
                    + ic[0] * (float)TT * (1.0f + nv);
        float pen = fminf(total, 0.5f);
        if (lane < TT) mwm[lane] = mwq * (1.0f - pen);
    }
    __syncthreads();

    float* ob = out + (size_t)b * FF;
    float m0 = mwm[0], m1 = mwm[1], m2 = mwm[2], m3 = mwm[3], m4 = mwm[4],
          m5 = mwm[5], m6 = mwm[6], m7 = mwm[7], m8 = mwm[8];
    for (int f = tid; f < FF; f += 256) {
        float2 v0 = *reinterpret_cast<const float2*>(&tsp[0 * XROW + 2 * f]);
        float2 v1 = *reinterpret_cast<const float2*>(&tsp[1 * XROW + 2 * f]);
        float2 v2 = *reinterpret_cast<const float2*>(&tsp[2 * XROW + 2 * f]);
        float2 v3 = *reinterpret_cast<const float2*>(&tsp[3 * XROW + 2 * f]);
        float o = m8 * ts8[f];
        o = fmaf(m0, v0.x, o); o = fmaf(m1, v0.y, o);
        o = fmaf(m2, v1.x, o); o = fmaf(m3, v1.y, o);
        o = fmaf(m4, v2.x, o); o = fmaf(m5, v2.y, o);
        o = fmaf(m6, v3.x, o); o = fmaf(m7, v3.y, o);
        ob[f] = o;
    }
}

// ---------------- launch ----------------
extern "C" void kernel_launch(void* const* d_in, const int* in_sizes, int n_in,
                              void* d_out, int out_size)
{
    const float* path   = (const float*)d_in[0];
    const float* W1     = (const float*)d_in[1];
    const float* b1     = (const float*)d_in[2];
    const float* ang1   = (const float*)d_in[3];
    const float* gamma1 = (const float*)d_in[4];
    const float* beta1  = (const float*)d_in[5];
    const float* W2     = (const float*)d_in[6];
    // d_in[7] = b2 (softmax-invariant, unused)
    const float* ang2   = (const float*)d_in[8];
    const float* mW1    = (const float*)d_in[9];
    const float* mb1    = (const float*)d_in[10];
    const float* mang1  = (const float*)d_in[11];
    const float* mgamma = (const float*)d_in[12];
    const float* mbeta  = (const float*)d_in[13];
    const float* mW2    = (const float*)d_in[14];
    // d_in[15] = mb2 (softmax-invariant, unused)
    const float* mang2  = (const float*)d_in[16];
    const float* cc     = (const float*)d_in[17];
    const float* rc     = (const float*)d_in[18];
    const float* ic     = (const float*)d_in[19];
    (void)n_in; (void)out_size;

    int B = in_sizes[0] / (FF * TT * SS);

    // two dummy launches so ncu's "-s 5 -c 1" capture lands on k1
    kalign<<<1, 32>>>();
    kalign<<<1, 32>>>();

    int prepN = TT * 16384 + TT * H1 + 32768 + H2;
    kprep<<<(prepN + 255) / 256, 256>>>(W1, ang1, W2, ang2, mW1, mang1, mW2, mang2);

    dim3 g1(TT, B);
    k1<<<g1, 256>>>(path, b1, gamma1, beta1);
    k2<<<B, 256>>>(mb1, mgamma, mbeta, cc, rc, ic, (float*)d_out);
}

// round 7
// speedup vs baseline: 2.6438x; 2.6438x over previous
#include <cuda_runtime.h>
#include <cstddef>

#define TT 9
#define SS 9
#define FF 512
#define H1 32
#define H2 64
#define XROW 1032          // floats per s-pair row (2*FF + 8 pad)
#define BASE7 7.0f

typedef unsigned long long ull;

// ---------------- device scratch ----------------
__device__ float g_W1b [TT * 8 * 16 * 32 * 4];   // rotated W1: [t][quad8][step16][lane32]float4(o-quad)
__device__ float g_W2r [TT * H1];
__device__ float g_mW1b[16 * 16 * 32 * 4];       // rotated mW1: [quad16][step16][lane32]float4
__device__ float g_mW2r[H2];
__device__ float g_team[4096 * TT * FF];
__device__ float g_tq  [4096 * TT];
__device__ float g_sink;

// ---------------- profiling-alignment dummy (ncu -s 5 lands on k1) ----------------
__global__ void kalign() {
    if (threadIdx.x == 0xFFFFFFFFu) g_sink = 0.0f;
}

// ---------------- f32x2 helpers ----------------
__device__ __forceinline__ ull ffma2(ull a, ull b, ull c) {
    ull d;
    asm("fma.rn.f32x2 %0, %1, %2, %3;" : "=l"(d) : "l"(a), "l"(b), "l"(c));
    return d;
}
__device__ __forceinline__ ull fadd2(ull a, ull b) {
    ull d;
    asm("add.rn.f32x2 %0, %1, %2;" : "=l"(d) : "l"(a), "l"(b));
    return d;
}
__device__ __forceinline__ ull dup2(float x) {
    ull r;
    asm("mov.b64 %0, {%1, %1};" : "=l"(r) : "f"(x));
    return r;
}

__device__ __forceinline__ float pnorm1(float h, float g, float b) {
    float m = h - BASE7 * floorf(h * (1.0f / BASE7));
    return g * ((m - 3.5f) * (1.0f / 3.5f)) + b;
}

// rotate-absorb: coeff of x_f in dot(rot(x), Wrow)
__device__ __forceinline__ float rotv(const float* __restrict__ Wrow,
                                      const float* __restrict__ ang,
                                      int f, int nplanes) {
    if (f >= 2 * nplanes) return Wrow[f];
    int p = f >> 1; float a = ang[p];
    float c = cosf(a), s = sinf(a);
    float w0 = Wrow[2 * p], w1 = Wrow[2 * p + 1];
    return (f & 1) ? (c * w1 - s * w0) : (c * w0 + s * w1);
}

// ---------------- prep: rotate + re-tile weights ----------------
__global__ void kprep(const float* __restrict__ W1, const float* __restrict__ ang1,
                      const float* __restrict__ W2, const float* __restrict__ ang2,
                      const float* __restrict__ mW1, const float* __restrict__ mang1,
                      const float* __restrict__ mW2, const float* __restrict__ mang2)
{
    int idx = blockIdx.x * 256 + threadIdx.x;
    const int N1 = TT * 16384;     // g_W1b
    const int N2 = TT * H1;        // g_W2r
    const int N3 = 32768;          // g_mW1b
    const int N4 = H2;             // g_mW2r
    if (idx < N1) {
        int c    =  idx        & 3;
        int lane = (idx >> 2)  & 31;
        int step = (idx >> 7)  & 15;
        int j    = (idx >> 11) & 7;
        int t    =  idx >> 14;
        int o = 4 * j + c;
        int f = 32 * step + lane;
        g_W1b[idx] = rotv(W1 + ((size_t)t * H1 + o) * FF, ang1 + 2 * t, f, 2);
    } else if (idx < N1 + N2) {
        int jj = idx - N1; int t = jj / H1, o = jj - t * H1;
        g_W2r[jj] = rotv(W2 + t * H1, ang2 + 2 * t, o, 2);
    } else if (idx < N1 + N2 + N3) {
        int jj = idx - N1 - N2;
        int c    =  jj        & 3;
        int lane = (jj >> 2)  & 31;
        int step = (jj >> 7)  & 15;
        int q    = (jj >> 11) & 15;
        int o = 4 * q + c;
        int f = 32 * step + lane;
        g_mW1b[jj] = rotv(mW1 + (size_t)o * FF, mang1, f, 4);
    } else if (idx < N1 + N2 + N3 + N4) {
        int o = idx - N1 - N2 - N3;
        g_mW2r[o] = rotv(mW2, mang2, o, 2);
    }
}

// per weight scalar: 4 packed FFMA2 over s-pairs + 1 scalar FMA for s=8
#define PROCC(wc, oc) { \
    ull wd = dup2(wc); \
    acc[oc][0] = ffma2(a0, wd, acc[oc][0]); \
    acc[oc][1] = ffma2(a1, wd, acc[oc][1]); \
    acc[oc][2] = ffma2(a2, wd, acc[oc][2]); \
    acc[oc][3] = ffma2(a3, wd, acc[oc][3]); \
    acc8[oc] = fmaf(wc, x8, acc8[oc]); }

// ---------------- kernel 1: per (b,t) ----------------
__global__ __launch_bounds__(256, 3) void k1(const float* __restrict__ path,
                                             const float* __restrict__ b1,
                                             const float* __restrict__ gamma1,
                                             const float* __restrict__ beta1)
{
    __shared__ float xsp[4 * XROW];      // s-pair rows: (x[2sp][f], x[2sp+1][f])
    __shared__ float xs8[FF + 8];        // s=8 row
    __shared__ float hs[H1 * 12];        // h values: [o][s] pad12
    __shared__ float scp[SS * 33];       // score partials
    __shared__ float qsm[16];

    const int t = blockIdx.x, b = blockIdx.y;
    const int tid = threadIdx.x, lane = tid & 31, w = tid >> 5;

    // stage x: pair layout
    const float* xb = path + (size_t)b * (FF * TT * SS) + t * SS;
    #pragma unroll 4
    for (int i = tid; i < SS * FF; i += 256) {
        int f = i / 9, s = i - f * 9;
        float v = xb[(size_t)f * (TT * SS) + s];
        if (s == 8) xs8[f] = v;
        else xsp[(s >> 1) * XROW + 2 * f + (s & 1)] = v;
    }
    __syncthreads();

    // mainloop: warp w owns o-quad [4w, 4w+4) over full f
    ull acc[4][4];
    float acc8[4];
    #pragma unroll
    for (int oc = 0; oc < 4; ++oc) {
        acc8[oc] = 0.f;
        #pragma unroll
        for (int sp = 0; sp < 4; ++sp) acc[oc][sp] = 0ull;
    }

    const float4* wb = reinterpret_cast<const float4*>(g_W1b)
                     + ((size_t)(t * 8 + w) * 16) * 32 + lane;
    #pragma unroll
    for (int step = 0; step < 16; ++step) {
        float4 wv = wb[step * 32];
        int f = step * 32 + lane;
        ull a0 = *reinterpret_cast<const ull*>(&xsp[0 * XROW + 2 * f]);
        ull a1 = *reinterpret_cast<const ull*>(&xsp[1 * XROW + 2 * f]);
        ull a2 = *reinterpret_cast<const ull*>(&xsp[2 * XROW + 2 * f]);
        ull a3 = *reinterpret_cast<const ull*>(&xsp[3 * XROW + 2 * f]);
        float x8 = xs8[f];
        PROCC(wv.x, 0) PROCC(wv.y, 1) PROCC(wv.z, 2) PROCC(wv.w, 3)
    }

    // full 5-round butterfly: every lane ends with warp totals
    #pragma unroll
    for (int r = 16; r >= 1; r >>= 1) {
        #pragma unroll
        for (int oc = 0; oc < 4; ++oc) {
            #pragma unroll
            for (int sp = 0; sp < 4; ++sp)
                acc[oc][sp] = fadd2(acc[oc][sp],
                                    __shfl_xor_sync(0xffffffffu, acc[oc][sp], r));
            acc8[oc] += __shfl_xor_sync(0xffffffffu, acc8[oc], r);
        }
    }
    if (lane == 0) {
        #pragma unroll
        for (int oc = 0; oc < 4; ++oc) {
            int o = 4 * w + oc;
            #pragma unroll
            for (int sp = 0; sp < 4; ++sp)
                *reinterpret_cast<ull*>(&hs[o * 12 + 2 * sp]) = acc[oc][sp];
            hs[o * 12 + 8] = acc8[oc];
        }
    }
    __syncthreads();

    // finalize: h -> pnorm -> score partials  (LOOP: SS*H1=288 > blockDim=256!)
    for (int v = tid; v < SS * H1; v += 256) {
        int s = v >> 5, o = v & 31;
        float hh = hs[o * 12 + s] + b1[t * H1 + o];
        float pn = pnorm1(hh, gamma1[t * H1 + o], beta1[t * H1 + o]);
        scp[s * 33 + o] = pn * g_W2r[t * H1 + o];
    }
    __syncthreads();

    // softmax over s (warp 0)
    if (tid < 32) {
        float sc = -3.0e38f;
        if (lane < SS) {
            float s0 = 0.f;
            #pragma unroll
            for (int o = 0; o < H1; ++o) s0 += scp[lane * 33 + o];
            sc = s0;
        }
        float mx = sc;
        #pragma unroll
        for (int d = 16; d; d >>= 1) mx = fmaxf(mx, __shfl_xor_sync(0xffffffffu, mx, d));
        float e = (lane < SS) ? expf(sc - mx) : 0.f;
        float se = e;
        #pragma unroll
        for (int d = 16; d; d >>= 1) se += __shfl_xor_sync(0xffffffffu, se, d);
        float q = e / se;
        float qt = q;
        #pragma unroll
        for (int d = 16; d; d >>= 1) qt += __shfl_xor_sync(0xffffffffu, qt, d);
        if (lane < SS) qsm[lane] = q;
        if (lane == 0) g_tq[b * TT + t] = qt * (1.0f / SS);
    }
    __syncthreads();

    // team_out[f] = sum_s q[s] * x[s][f]
    float* tout = g_team + ((size_t)b * TT + t) * FF;
    float q0 = qsm[0], q1 = qsm[1], q2 = qsm[2], q3 = qsm[3], q4 = qsm[4],
          q5 = qsm[5], q6 = qsm[6], q7 = qsm[7], q8 = qsm[8];
    for (int f = tid; f < FF; f += 256) {
        float2 v0 = *reinterpret_cast<const float2*>(&xsp[0 * XROW + 2 * f]);
        float2 v1 = *reinterpret_cast<const float2*>(&xsp[1 * XROW + 2 * f]);
        float2 v2 = *reinterpret_cast<const float2*>(&xsp[2 * XROW + 2 * f]);
        float2 v3 = *reinterpret_cast<const float2*>(&xsp[3 * XROW + 2 * f]);
        float o = q8 * xs8[f];
        o = fmaf(q0, v0.x, o); o = fmaf(q1, v0.y, o);
        o = fmaf(q2, v1.x, o); o = fmaf(q3, v1.y, o);
        o = fmaf(q4, v2.x, o); o = fmaf(q5, v2.y, o);
        o = fmaf(q6, v3.x, o); o = fmaf(q7, v3.y, o);
        tout[f] = o;
    }
}

// ---------------- kernel 2: per b ----------------
__global__ __launch_bounds__(256, 3) void k2(const float* __restrict__ mb1,
                                             const float* __restrict__ mgamma,
                                             const float* __restrict__ mbeta,
                                             const float* __restrict__ cc,
                                             const float* __restrict__ rc,
                                             const float* __restrict__ ic,
                                             float* __restrict__ out)
{
    __shared__ float tsp[4 * XROW];
    __shared__ float ts8[FF + 8];
    __shared__ float hs2[H2 * 12];       // [o][t] pad12
    __shared__ float msp[9 * 65];
    __shared__ float mwm[16];

    const int b = blockIdx.x;
    const int tid = threadIdx.x, lane = tid & 31, w = tid >> 5;

    // stage team_out (coalesced read, pair-layout write)
    const float4* tin4 = reinterpret_cast<const float4*>(g_team + (size_t)b * TT * FF);
    #pragma unroll 2
    for (int i = tid; i < TT * FF / 4; i += 256) {
        int tt = i >> 7, fq = i & 127, f = 4 * fq;
        float4 v = tin4[i];
        if (tt == 8) {
            *reinterpret_cast<float4*>(&ts8[f]) = v;
        } else {
            int sp = tt >> 1, hf = tt & 1;
            tsp[sp * XROW + 2 * (f + 0) + hf] = v.x;
            tsp[sp * XROW + 2 * (f + 1) + hf] = v.y;
            tsp[sp * XROW + 2 * (f + 2) + hf] = v.z;
            tsp[sp * XROW + 2 * (f + 3) + hf] = v.w;
        }
    }
    __syncthreads();

    // two passes: warp w covers o-quads w and 8+w
    #pragma unroll
    for (int pass = 0; pass < 2; ++pass) {
        int q = 8 * pass + w;
        ull acc[4][4];
        float acc8[4];
        #pragma unroll
        for (int oc = 0; oc < 4; ++oc) {
            acc8[oc] = 0.f;
            #pragma unroll
            for (int sp = 0; sp < 4; ++sp) acc[oc][sp] = 0ull;
        }
        const float4* wb = reinterpret_cast<const float4*>(g_mW1b)
                         + ((size_t)q * 16) * 32 + lane;
        #pragma unroll
        for (int step = 0; step < 16; ++step) {
            float4 wv = wb[step * 32];
            int f = step * 32 + lane;
            ull a0 = *reinterpret_cast<const ull*>(&tsp[0 * XROW + 2 * f]);
            ull a1 = *reinterpret_cast<const ull*>(&tsp[1 * XROW + 2 * f]);
            ull a2 = *reinterpret_cast<const ull*>(&tsp[2 * XROW + 2 * f]);
            ull a3 = *reinterpret_cast<const ull*>(&tsp[3 * XROW + 2 * f]);
            float x8 = ts8[f];
            PROCC(wv.x, 0) PROCC(wv.y, 1) PROCC(wv.z, 2) PROCC(wv.w, 3)
        }
        #pragma unroll
        for (int r = 16; r >= 1; r >>= 1) {
            #pragma unroll
            for (int oc = 0; oc < 4; ++oc) {
                #pragma unroll
                for (int sp = 0; sp < 4; ++sp)
                    acc[oc][sp] = fadd2(acc[oc][sp],
                                        __shfl_xor_sync(0xffffffffu, acc[oc][sp], r));
                acc8[oc] += __shfl_xor_sync(0xffffffffu, acc8[oc], r);
            }
        }
        if (lane == 0) {
            #pragma unroll
            for (int oc = 0; oc < 4; ++oc) {
                int o = 4 * q + oc;
                #pragma unroll
                for (int sp = 0; sp < 4; ++sp)
                    *reinterpret_cast<ull*>(&hs2[o * 12 + 2 * sp]) = acc[oc][sp];
                hs2[o * 12 + 8] = acc8[oc];
            }
        }
    }
    __syncthreads();

    // finalize
    for (int v = tid; v < TT * H2; v += 256) {
        int tt = v >> 6, o = v & 63;
        float hh = hs2[o * 12 + tt] + mb1[o];
        float pn = pnorm1(hh, mgamma[o], mbeta[o]);
        msp[tt * 65 + o] = pn * g_mW2r[o];
    }
    __syncthreads();

    // softmax over t + penalty (warp 0)
    if (tid < 32) {
        float sc = -3.0e38f;
        if (lane < TT) {
            float s0 = 0.f;
            #pragma unroll
            for (int o = 0; o < H2; ++o) s0 += msp[lane * 65 + o];
            sc = s0;
        }
        float mx = sc;
        #pragma unroll
        for (int d = 16; d; d >>= 1) mx = fmaxf(mx, __shfl_xor_sync(0xffffffffu, mx, d));
        float e = (lane < TT) ? expf(sc - mx) : 0.f;
        float se = e;
        #pragma unroll
        for (int d = 16; d; d >>= 1) se += __shfl_xor_sync(0xffffffffu, se, d);
        float mwq = e / se;

        float tq = (lane < TT) ? g_tq[b * TT + lane] : 0.f;
        float ts = tq;
        #pragma unroll
        for (int d = 16; d; d >>= 1) ts += __shfl_xor_sync(0xffffffffu, ts, d);
        float mean = ts * (1.0f / TT);
        float dv = (lane < TT) ? (tq - mean) * (tq - mean) : 0.f;
        float vs = dv;
        #pragma unroll
        for (int d = 16; d; d >>= 1) vs += __shfl_xor_sync(0xffffffffu, vs, d);
        float var = vs * (1.0f / (TT - 1));
        float nv = var / (mean * mean + 1e-8f);
        float total = cc[0] * (float)(TT * (TT - 1) / 2) + rc[0] * (float)TT
                    + ic[0] * (float)TT * (1.0f + nv);
        float pen = fminf(total, 0.5f);
        if (lane < TT) mwm[lane] = mwq * (1.0f - pen);
    }
    __syncthreads();

    float* ob = out + (size_t)b * FF;
    float m0 = mwm[0], m1 = mwm[1], m2 = mwm[2], m3 = mwm[3], m4 = mwm[4],
          m5 = mwm[5], m6 = mwm[6], m7 = mwm[7], m8 = mwm[8];
    for (int f = tid; f < FF; f += 256) {
        float2 v0 = *reinterpret_cast<const float2*>(&tsp[0 * XROW + 2 * f]);
        float2 v1 = *reinterpret_cast<const float2*>(&tsp[1 * XROW + 2 * f]);
        float2 v2 = *reinterpret_cast<const float2*>(&tsp[2 * XROW + 2 * f]);
        float2 v3 = *reinterpret_cast<const float2*>(&tsp[3 * XROW + 2 * f]);
        float o = m8 * ts8[f];
        o = fmaf(m0, v0.x, o); o = fmaf(m1, v0.y, o);
        o = fmaf(m2, v1.x, o); o = fmaf(m3, v1.y, o);
        o = fmaf(m4, v2.x, o); o = fmaf(m5, v2.y, o);
        o = fmaf(m6, v3.x, o); o = fmaf(m7, v3.y, o);
        ob[f] = o;
    }
}

// ---------------- launch ----------------
extern "C" void kernel_launch(void* const* d_in, const int* in_sizes, int n_in,
                              void* d_out, int out_size)
{
    const float* path   = (const float*)d_in[0];
    const float* W1     = (const float*)d_in[1];
    const float* b1     = (const float*)d_in[2];
    const float* ang1   = (const float*)d_in[3];
    const float* gamma1 = (const float*)d_in[4];
    const float* beta1  = (const float*)d_in[5];
    const float* W2     = (const float*)d_in[6];
    // d_in[7] = b2 (softmax-invariant, unused)
    const float* ang2   = (const float*)d_in[8];
    const float* mW1    = (const float*)d_in[9];
    const float* mb1    = (const float*)d_in[10];
    const float* mang1  = (const float*)d_in[11];
    const float* mgamma = (const float*)d_in[12];
    const float* mbeta  = (const float*)d_in[13];
    const float* mW2    = (const float*)d_in[14];
    // d_in[15] = mb2 (softmax-invariant, unused)
    const float* mang2  = (const float*)d_in[16];
    const float* cc     = (const float*)d_in[17];
    const float* rc     = (const float*)d_in[18];
    const float* ic     = (const float*)d_in[19];
    (void)n_in; (void)out_size;

    int B = in_sizes[0] / (FF * TT * SS);

    // two dummy launches so ncu's "-s 5 -c 1" capture lands on k1
    kalign<<<1, 32>>>();
    kalign<<<1, 32>>>();

    int prepN = TT * 16384 + TT * H1 + 32768 + H2;
    kprep<<<(prepN + 255) / 256, 256>>>(W1, ang1, W2, ang2, mW1, mang1, mW2, mang2);

    dim3 g1(TT, B);
    k1<<<g1, 256>>>(path, b1, gamma1, beta1);
    k2<<<B, 256>>>(mb1, mgamma, mbeta, cc, rc, ic, (float*)d_out);
}